// round 5
// baseline (speedup 1.0000x reference)
#include <cuda_runtime.h>

// BiquadCoeffFilter: time-varying IIR(2) + FIR(2) with interpolated coefficients.
// Parallelized via chunked affine-map scan of the order-2 linear recurrence.
//
//   s[t] = (y[t], y[t-1]),  s[t] = A_t s[t-1] + (x[t], 0),
//   A_t = [[-a1_t, -a2_t], [1, 0]]
//
// Pass1: per-chunk transfer matrix P and zero-state response d.
// Combine: affine scan across chunks per row -> exact initial state per chunk.
// Pass2: re-run chunks with correct init, fuse FIR, write output.

#define NCTRL  256
#define NCOEF  5
#define CHUNK  64           // samples per chunk (thread-serial)
#define TPB    256          // threads per block, pass1/pass2
#define TPB2   256          // threads per block, combine
#define MAXCHUNKS 131072    // 32 rows * 262144/64
#define STAB   0.999f       // 1 - EPS, EPS = 1e-3

__device__ float g_P00[MAXCHUNKS], g_P01[MAXCHUNKS];
__device__ float g_P10[MAXCHUNKS], g_P11[MAXCHUNKS];
__device__ float g_D0 [MAXCHUNKS], g_D1 [MAXCHUNKS];
__device__ float g_S0 [MAXCHUNKS], g_S1 [MAXCHUNKS];

// Paired fast tanh: tanh(x) = (z-1)/(z+1), z = e^{2x}.
// Two tanh's share ONE reciprocal via r = 1/((z0+1)(z1+1)):
//   th0 = (z0-1)*(z1+1)*r ; th1 = (z1-1)*(z0+1)*r
// 3 MUFU (2x EX2 + 1x RCP) instead of 4. Abs err ~1e-7.
// Clamp |x|<=15 -> z in [1e-13,1e13], product in [1,1e26]: safe range.
__device__ __forceinline__ void fast_tanh2(float x0, float x1,
                                           float& th0, float& th1) {
    float c0 = fminf(fmaxf(x0, -15.0f), 15.0f);
    float c1 = fminf(fmaxf(x1, -15.0f), 15.0f);
    float z0 = __expf(2.0f * c0);
    float z1 = __expf(2.0f * c1);
    float p0 = z0 + 1.0f, m0 = z0 - 1.0f;
    float p1 = z1 + 1.0f, m1 = z1 - 1.0f;
    float r  = __frcp_rn(p0 * p1);
    th0 = m0 * p1 * r;
    th1 = m1 * p0 * r;
}

__device__ __forceinline__ void a_coeffs(float l0, float l1,
                                         float& a1, float& a2) {
    float th0, th1;
    fast_tanh2(l0, l1, th0, th1);
    a1 = 2.0f * STAB * th0;
    float aa = fabsf(a1);
    a2 = 0.5f * fmaf((2.0f - aa) * STAB, th1, aa);
}

// ---------------------------------------------------------------------------
// Pass 1: per-chunk (P, d) with zero initial state.
// grid: (chunks_per_row / TPB, B), block: TPB. One thread = one chunk.
// ---------------------------------------------------------------------------
__global__ void __launch_bounds__(TPB)
k_pass1(const float* __restrict__ x, const float* __restrict__ logits,
        int N, int chunks_per_row) {
    __shared__ float s_log[NCTRL * NCOEF];
    const int row = blockIdx.y;
    {
        const float* lg = logits + (size_t)row * (NCTRL * NCOEF);
        for (int i = threadIdx.x; i < NCTRL * NCOEF; i += TPB) s_log[i] = lg[i];
    }
    __syncthreads();

    const int chunk = blockIdx.x * TPB + threadIdx.x;
    if (chunk >= chunks_per_row) return;

    const int t0 = chunk * CHUNK;
    const float4* xr = (const float4*)(x + (size_t)row * N + t0);

    const float dw = (float)(NCTRL - 1) / (float)(N - 1);
    float tf  = (float)t0;
    float pos = tf * dw;
    int   i0  = (int)pos;
    float i0f = (float)i0;

    // Cache current segment's a-logits (coeff 0,1) and deltas.
    int i1 = min(i0 + 1, NCTRL - 1);
    float c0 = s_log[i0 * NCOEF + 0], c1 = s_log[i0 * NCOEF + 1];
    float e0 = s_log[i1 * NCOEF + 0] - c0;
    float e1 = s_log[i1 * NCOEF + 1] - c1;

    float p00 = 1.f, p01 = 0.f, p10 = 0.f, p11 = 1.f;
    float y1 = 0.f, y2 = 0.f;

    for (int k4 = 0; k4 < CHUNK / 4; k4++) {
        float4 xv4 = xr[k4];
        float xs[4] = {xv4.x, xv4.y, xv4.z, xv4.w};
        #pragma unroll
        for (int u = 0; u < 4; u++) {
            float p = tf * dw;
            if (p - i0f >= 1.0f) {           // rare: ~once per 1028 samples
                i0++; i0f += 1.0f;
                int ii1 = min(i0 + 1, NCTRL - 1);
                float nc0 = s_log[i0 * NCOEF + 0];
                float nc1 = s_log[i0 * NCOEF + 1];
                e0 = s_log[ii1 * NCOEF + 0] - nc0;
                e1 = s_log[ii1 * NCOEF + 1] - nc1;
                c0 = nc0; c1 = nc1;
            }
            float w  = p - i0f;
            float l0 = fmaf(w, e0, c0);
            float l1 = fmaf(w, e1, c1);

            float a1, a2;
            a_coeffs(l0, l1, a1, a2);

            // zero-state response
            float y = fmaf(-a2, y2, fmaf(-a1, y1, xs[u]));
            y2 = y1; y1 = y;

            // P <- A_t * P : row0' = -a1*row0 - a2*row1 ; row1' = row0
            float n00 = -fmaf(a1, p00, a2 * p10);
            float n01 = -fmaf(a1, p01, a2 * p11);
            p10 = p00; p11 = p01; p00 = n00; p01 = n01;

            tf += 1.0f;
        }
    }

    const int cidx = row * chunks_per_row + chunk;
    g_P00[cidx] = p00; g_P01[cidx] = p01;
    g_P10[cidx] = p10; g_P11[cidx] = p11;
    g_D0 [cidx] = y1;  g_D1 [cidx] = y2;   // state at chunk end (zero init)
}

// ---------------------------------------------------------------------------
// Combine: per-row affine scan over chunk maps; writes initial state per chunk.
// grid: B blocks, TPB2 threads, each thread serially composes
// chunks_per_row/TPB2 consecutive maps, then Hillis-Steele scan in shared.
// ---------------------------------------------------------------------------
__global__ void __launch_bounds__(TPB2)
k_combine(int chunks_per_row) {
    __shared__ float sP00[TPB2], sP01[TPB2], sP10[TPB2], sP11[TPB2];
    __shared__ float sD0[TPB2], sD1[TPB2];

    const int row = blockIdx.x;
    const int tid = threadIdx.x;
    const int per = chunks_per_row / TPB2;
    const int base = row * chunks_per_row + tid * per;

    // Compose own run of maps (apply in increasing time order; new map on left)
    float P00 = 1.f, P01 = 0.f, P10 = 0.f, P11 = 1.f, D0 = 0.f, D1 = 0.f;
    for (int j = 0; j < per; j++) {
        int c = base + j;
        float p00 = g_P00[c], p01 = g_P01[c], p10 = g_P10[c], p11 = g_P11[c];
        float d0 = g_D0[c], d1 = g_D1[c];
        float n00 = p00 * P00 + p01 * P10;
        float n01 = p00 * P01 + p01 * P11;
        float n10 = p10 * P00 + p11 * P10;
        float n11 = p10 * P01 + p11 * P11;
        float nd0 = p00 * D0 + p01 * D1 + d0;
        float nd1 = p10 * D0 + p11 * D1 + d1;
        P00 = n00; P01 = n01; P10 = n10; P11 = n11; D0 = nd0; D1 = nd1;
    }
    sP00[tid] = P00; sP01[tid] = P01; sP10[tid] = P10; sP11[tid] = P11;
    sD0[tid] = D0; sD1[tid] = D1;
    __syncthreads();

    // Inclusive scan (composition: own ∘ earlier)
    for (int off = 1; off < TPB2; off <<= 1) {
        float q00 = 0, q01 = 0, q10 = 0, q11 = 0, qd0 = 0, qd1 = 0;
        bool act = (tid >= off);
        if (act) {
            q00 = sP00[tid - off]; q01 = sP01[tid - off];
            q10 = sP10[tid - off]; q11 = sP11[tid - off];
            qd0 = sD0[tid - off];  qd1 = sD1[tid - off];
        }
        __syncthreads();
        if (act) {
            float n00 = P00 * q00 + P01 * q10;
            float n01 = P00 * q01 + P01 * q11;
            float n10 = P10 * q00 + P11 * q10;
            float n11 = P10 * q01 + P11 * q11;
            float nd0 = P00 * qd0 + P01 * qd1 + D0;
            float nd1 = P10 * qd0 + P11 * qd1 + D1;
            P00 = n00; P01 = n01; P10 = n10; P11 = n11; D0 = nd0; D1 = nd1;
            sP00[tid] = P00; sP01[tid] = P01; sP10[tid] = P10; sP11[tid] = P11;
            sD0[tid] = D0; sD1[tid] = D1;
        }
        __syncthreads();
    }

    // Global initial state is (0,0), so the exclusive-prefix state is just D.
    float s0 = (tid == 0) ? 0.f : sD0[tid - 1];
    float s1 = (tid == 0) ? 0.f : sD1[tid - 1];
    for (int j = 0; j < per; j++) {
        int c = base + j;
        g_S0[c] = s0; g_S1[c] = s1;
        float p00 = g_P00[c], p01 = g_P01[c], p10 = g_P10[c], p11 = g_P11[c];
        float t0n = p00 * s0 + p01 * s1 + g_D0[c];
        float t1n = p10 * s0 + p11 * s1 + g_D1[c];
        s0 = t0n; s1 = t1n;
    }
}

// ---------------------------------------------------------------------------
// Pass 2: re-run each chunk with correct initial state, fuse FIR, write out.
// ---------------------------------------------------------------------------
__global__ void __launch_bounds__(TPB)
k_pass2(const float* __restrict__ x, const float* __restrict__ logits,
        float* __restrict__ out, int N, int chunks_per_row) {
    __shared__ float s_log[NCTRL * NCOEF];
    const int row = blockIdx.y;
    {
        const float* lg = logits + (size_t)row * (NCTRL * NCOEF);
        for (int i = threadIdx.x; i < NCTRL * NCOEF; i += TPB) s_log[i] = lg[i];
    }
    __syncthreads();

    const int chunk = blockIdx.x * TPB + threadIdx.x;
    if (chunk >= chunks_per_row) return;

    const int t0 = chunk * CHUNK;
    const float4* xr = (const float4*)(x + (size_t)row * N + t0);
    float4* outr = (float4*)(out + (size_t)row * N + t0);

    const float dw = (float)(NCTRL - 1) / (float)(N - 1);
    float tf  = (float)t0;
    float pos = tf * dw;
    int   i0  = (int)pos;
    float i0f = (float)i0;

    // Cache full 5-logit segment + deltas.
    int i1 = min(i0 + 1, NCTRL - 1);
    float c0 = s_log[i0 * NCOEF + 0], c1 = s_log[i0 * NCOEF + 1];
    float c2 = s_log[i0 * NCOEF + 2], c3 = s_log[i0 * NCOEF + 3];
    float c4 = s_log[i0 * NCOEF + 4];
    float e0 = s_log[i1 * NCOEF + 0] - c0;
    float e1 = s_log[i1 * NCOEF + 1] - c1;
    float e2 = s_log[i1 * NCOEF + 2] - c2;
    float e3 = s_log[i1 * NCOEF + 3] - c3;
    float e4 = s_log[i1 * NCOEF + 4] - c4;

    const int cidx = row * chunks_per_row + chunk;
    float y1 = g_S0[cidx];   // y[t0-1]
    float y2 = g_S1[cidx];   // y[t0-2]

    for (int k4 = 0; k4 < CHUNK / 4; k4++) {
        float4 xv4 = xr[k4];
        float xs[4] = {xv4.x, xv4.y, xv4.z, xv4.w};
        float os[4];
        #pragma unroll
        for (int u = 0; u < 4; u++) {
            float p = tf * dw;
            if (p - i0f >= 1.0f) {
                i0++; i0f += 1.0f;
                int ii1 = min(i0 + 1, NCTRL - 1);
                float nc0 = s_log[i0 * NCOEF + 0];
                float nc1 = s_log[i0 * NCOEF + 1];
                float nc2 = s_log[i0 * NCOEF + 2];
                float nc3 = s_log[i0 * NCOEF + 3];
                float nc4 = s_log[i0 * NCOEF + 4];
                e0 = s_log[ii1 * NCOEF + 0] - nc0;
                e1 = s_log[ii1 * NCOEF + 1] - nc1;
                e2 = s_log[ii1 * NCOEF + 2] - nc2;
                e3 = s_log[ii1 * NCOEF + 3] - nc3;
                e4 = s_log[ii1 * NCOEF + 4] - nc4;
                c0 = nc0; c1 = nc1; c2 = nc2; c3 = nc3; c4 = nc4;
            }
            float w  = p - i0f;
            float l0 = fmaf(w, e0, c0);
            float l1 = fmaf(w, e1, c1);
            float b0 = fmaf(w, e2, c2);
            float b1 = fmaf(w, e3, c3);
            float b2 = fmaf(w, e4, c4);

            float a1, a2;
            a_coeffs(l0, l1, a1, a2);

            float y = fmaf(-a2, y2, fmaf(-a1, y1, xs[u]));
            // FIR uses y[t], y[t-1], y[t-2] (zero-padded at t<0 handled by init)
            os[u] = fmaf(b2, y2, fmaf(b1, y1, b0 * y));
            y2 = y1; y1 = y;
            tf += 1.0f;
        }
        outr[k4] = make_float4(os[0], os[1], os[2], os[3]);
    }
}

// ---------------------------------------------------------------------------
extern "C" void kernel_launch(void* const* d_in, const int* in_sizes, int n_in,
                              void* d_out, int out_size) {
    const float* x      = (const float*)d_in[0];
    const float* logits = (const float*)d_in[1];
    float* out = (float*)d_out;

    int B = in_sizes[1] / (NCTRL * NCOEF);   // 32
    int N = in_sizes[0] / B;                 // 262144
    int chunks_per_row = N / CHUNK;          // 4096

    dim3 g1(chunks_per_row / TPB, B);        // (16, 32)
    k_pass1 <<<g1, TPB>>>(x, logits, N, chunks_per_row);
    k_combine<<<B, TPB2>>>(chunks_per_row);
    k_pass2 <<<g1, TPB>>>(x, logits, out, N, chunks_per_row);
}